// round 13
// baseline (speedup 1.0000x reference)
#include <cuda_runtime.h>
#include <cuda_fp16.h>
#include <cstdint>

#define B_ROWS   65536
#define OUT_N    2048
#define IN_K     64
#define BM       128
#define BN       64
#define NTHREADS 256
#define NT       8              // col tiles per CTA
#define BUFSTR   8704           // C buffer stride: 8 KB tile + 512 B aux
#define STAGE_OFF 33792         // output staging: 128 rows x 256 B (XOR-swizzled)
#define SMEM_MAIN (STAGE_OFF + BM * 256)   // 66560

// ---------------- scratch (__device__ globals: allocation-free) ----------------
__device__ __half g_X[(size_t)B_ROWS * IN_K];
__device__ __half g_C[(size_t)OUT_N * IN_K];
__device__ float g_x2[B_ROWS];     // exact ||x||^2 (fp32)
__device__ float g_c2[OUT_N];      // exact ||c||^2 (fp32)
__device__ float g_e2[OUT_N];      // -exp(-2*log_sigma) * log2(e)

// ---------------- PTX helpers (sm_80-era only) ----------------
__device__ __forceinline__ uint32_t smem_u32(const void* p) {
    uint32_t a;
    asm("{ .reg .u64 t; cvta.to.shared.u64 t, %1; cvt.u32.u64 %0, t; }" : "=r"(a) : "l"(p));
    return a;
}
__device__ __forceinline__ void cp16(uint32_t s, const void* g) {
    asm volatile("{ .reg .u64 ga; cvta.to.global.u64 ga, %1; cp.async.cg.shared.global [%0], [ga], 16; }"
                 :: "r"(s), "l"(g) : "memory");
}
#define CP_COMMIT() asm volatile("cp.async.commit_group;" ::: "memory")
#define CP_WAIT1()  asm volatile("cp.async.wait_group 1;" ::: "memory")
#define CP_WAIT2()  asm volatile("cp.async.wait_group 2;" ::: "memory")

#define STS64(a, v0, v1) \
    asm volatile("st.shared.v2.f32 [%0], {%1, %2};" :: "r"(a), "f"(v0), "f"(v1) : "memory")
#define LDS128(v, a) \
    asm volatile("ld.shared.v4.f32 {%0,%1,%2,%3}, [%4];" \
        : "=f"((v).x), "=f"((v).y), "=f"((v).z), "=f"((v).w) : "r"(a))

#define LDSM4(r, a) \
    asm volatile("ldmatrix.sync.aligned.m8n8.x4.shared.b16 {%0,%1,%2,%3}, [%4];" \
        : "=r"((r)[0]), "=r"((r)[1]), "=r"((r)[2]), "=r"((r)[3]) : "r"(a))

#define MMA16816(d, a, b0, b1) \
    asm volatile("mma.sync.aligned.m16n8k16.row.col.f32.f16.f16.f32 " \
        "{%0,%1,%2,%3}, {%4,%5,%6,%7}, {%8,%9}, {%0,%1,%2,%3};" \
        : "+f"((d)[0]), "+f"((d)[1]), "+f"((d)[2]), "+f"((d)[3]) \
        : "r"((a)[0]), "r"((a)[1]), "r"((a)[2]), "r"((a)[3]), "r"(b0), "r"(b1))

// ---------------- prep: fp32 -> fp16 + exact norms ----------------
__global__ void prep_all(const float* __restrict__ inp,
                         const float* __restrict__ cen,
                         const float* __restrict__ ls) {
    const int b = blockIdx.x;
    const bool is_c = (b >= 4096);
    const int g = (is_c ? (b - 4096) : b) * blockDim.x + threadIdx.x;
    const int row = g >> 4, seg = g & 15;

    const float* src = is_c ? cen : inp;
    const float4 v = *(const float4*)(src + (size_t)row * IN_K + seg * 4);
    float vv[4] = {v.x, v.y, v.z, v.w};
    float s = 0.f;
    __half h[4];
    #pragma unroll
    for (int i = 0; i < 4; i++) {
        s = fmaf(vv[i], vv[i], s);
        h[i] = __float2half_rn(vv[i]);
    }
    uint2 hp;
    memcpy(&hp, h, 8);
    const size_t base = (size_t)row * IN_K + seg * 4;
    if (is_c) *(uint2*)(g_C + base) = hp;
    else      *(uint2*)(g_X + base) = hp;

    #pragma unroll
    for (int m = 1; m <= 8; m <<= 1) s += __shfl_xor_sync(~0u, s, m);
    if (seg == 0) {
        if (is_c) {
            g_c2[row] = s;
            g_e2[row] = -1.4426950408889634f * expf(-2.f * ls[row]);
        } else {
            g_x2[row] = s;
        }
    }
}

// ---------------- main ----------------
// smem layout (byte offsets):
//   0      sX  : [128][64] fp16 swizzled                 16384
//   16384  buf0: C tile 8192 + c2 256 + e2 256            8704
//   25088  buf1: same                                      8704
//   33792  staging: 128 rows x 256 B, XOR-swizzled       32768
extern __shared__ char smem_raw[];

__global__ __launch_bounds__(NTHREADS, 2)
void rbf_hmma(float* __restrict__ out) {
    const int tid = threadIdx.x;
    const int bid = blockIdx.x;
    const int row0 = (bid >> 2) * BM;
    const int ct0  = (bid & 3) * NT;

    const uint32_t sb  = smem_u32(smem_raw);
    const uint32_t sXu = sb;

    auto load_C = [&](int ct, int buf) {
        const uint32_t dst = sb + 16384 + buf * BUFSTR;
        #pragma unroll
        for (int i = 0; i < 2; i++) {
            int u = tid + i * NTHREADS;
            int r = u >> 3, c = u & 7;
            cp16(dst + r * 128 + ((c ^ (r & 7)) << 4),
                 g_C + (size_t)(ct * BN + r) * IN_K + c * 8);
        }
        if (tid < 16)
            cp16(dst + 8192 + tid * 16, g_c2 + ct * BN + tid * 4);
        else if (tid < 32)
            cp16(dst + 8192 + 256 + (tid - 16) * 16, g_e2 + ct * BN + (tid - 16) * 4);
    };

    // ---- prologue: X (group), C0 (group), C1 (group) ----
    #pragma unroll
    for (int i = 0; i < 4; i++) {
        int u = tid + i * NTHREADS;
        int r = u >> 3, c = u & 7;
        cp16(sXu + r * 128 + ((c ^ (r & 7)) << 4),
             g_X + (size_t)(row0 + r) * IN_K + c * 8);
    }
    CP_COMMIT();
    load_C(ct0, 0);
    CP_COMMIT();
    load_C(ct0 + 1, 1);
    CP_COMMIT();

    // ---- warp tiling: 8 warps = 4 (M) x 2 (N); warp tile 32x32 ----
    const int l   = tid & 31;
    const int wid = tid >> 5;
    const int wr  = wid & 3;
    const int wc  = wid >> 2;

    uint32_t abase[2];
    {
        int hb = l >> 4;
        #pragma unroll
        for (int mi = 0; mi < 2; mi++) {
            int row = wr * 32 + mi * 16 + (l & 15);
            abase[mi] = row * 128 + ((hb ^ (row & 7)) << 4);
        }
    }
    uint32_t bbase[2];
    {
        int m = l >> 3;
        int hb = m & 1;
        #pragma unroll
        for (int q = 0; q < 2; q++) {
            int n = wc * 32 + (2 * q + (m >> 1)) * 8 + (l & 7);
            bbase[q] = n * 128 + ((hb ^ (n & 7)) << 4);
        }
    }

    // ---- wait for X; hoist A fragments (CTA-invariant across col tiles) ----
    CP_WAIT2();
    __syncthreads();
    uint32_t afrag[4][2][4];
    #pragma unroll
    for (int ks = 0; ks < 4; ks++) {
        const uint32_t kx = (uint32_t)ks << 5;
        LDSM4(afrag[ks][0], sXu + (abase[0] ^ kx));
        LDSM4(afrag[ks][1], sXu + (abase[1] ^ kx));
    }
    // hoist x2 for this thread's 4 fragment rows
    const int rl0 = wr * 32 + (l >> 2);
    float x2v[4];
    x2v[0] = g_x2[row0 + rl0];
    x2v[1] = g_x2[row0 + rl0 + 8];
    x2v[2] = g_x2[row0 + rl0 + 16];
    x2v[3] = g_x2[row0 + rl0 + 24];

    // staging constants
    const int sw = (l >> 2) << 2;                 // XOR swizzle (in 8B units)
    const int ub = wc * 16 + (l & 3);             // base 8B unit (+ j*4)
    // readback constants
    const int g_u  = (tid & 15) * 2;              // even 8B unit for LDS.128

    #pragma unroll 1
    for (int t = 0; t < NT; t++) {
        const int buf = t & 1;
        const uint32_t cbuf = sb + 16384 + buf * BUFSTR;
        const int col0 = (ct0 + t) * BN;

        CP_WAIT1();                 // current C buf ready
        __syncthreads();            // + staging reuse guard

        float acc[2][4][4];
        #pragma unroll
        for (int mi = 0; mi < 2; mi++)
            #pragma unroll
            for (int j = 0; j < 4; j++)
                #pragma unroll
                for (int q = 0; q < 4; q++) acc[mi][j][q] = 0.f;

        #pragma unroll
        for (int ks = 0; ks < 4; ks++) {
            const uint32_t kx = (uint32_t)ks << 5;
            uint32_t b[2][4];
            LDSM4(b[0], cbuf + (bbase[0] ^ kx));
            LDSM4(b[1], cbuf + (bbase[1] ^ kx));
            #pragma unroll
            for (int j = 0; j < 4; j++) {
                uint32_t b0 = b[j >> 1][(j & 1) * 2];
                uint32_t b1 = b[j >> 1][(j & 1) * 2 + 1];
                MMA16816(acc[0][j], afrag[ks][0], b0, b1);
                MMA16816(acc[1][j], afrag[ks][1], b0, b1);
            }
        }

        // ---- epilogue: exp2((x2 - 2*dot + c2) * e2) -> swizzled staging ----
        const float* c2s = (const float*)(smem_raw + 16384 + buf * BUFSTR + 8192);
        const float* e2s = c2s + 64;
        #pragma unroll
        for (int mi = 0; mi < 2; mi++) {
            const float x2a = x2v[mi * 2];
            const float x2b = x2v[mi * 2 + 1];
            const uint32_t ra = sb + STAGE_OFF + (uint32_t)(rl0 + mi * 16) * 256;
            const uint32_t rb = ra + 8 * 256;
            #pragma unroll
            for (int j = 0; j < 4; j++) {
                const int c = wc * 32 + j * 8 + 2 * (l & 3);
                const float c20 = c2s[c],  c21 = c2s[c + 1];
                const float e0  = e2s[c],  e1  = e2s[c + 1];
                const float* A  = acc[mi][j];
                float s0 = fmaxf(fmaf(-2.f, A[0], x2a + c20), 0.f);
                float s1 = fmaxf(fmaf(-2.f, A[1], x2a + c21), 0.f);
                float s2 = fmaxf(fmaf(-2.f, A[2], x2b + c20), 0.f);
                float s3 = fmaxf(fmaf(-2.f, A[3], x2b + c21), 0.f);
                const uint32_t uo = (uint32_t)(((ub + j * 4) ^ sw) << 3);
                STS64(ra + uo, exp2f(s0 * e0), exp2f(s1 * e1));
                STS64(rb + uo, exp2f(s2 * e0), exp2f(s3 * e1));
            }
        }

        __syncthreads();

        // ---- coalesced readback + STG.128 (512 B contiguous per warp) ----
        #pragma unroll
        for (int pass = 0; pass < 8; pass++) {
            const int grow = pass * 16 + (tid >> 4);
            const uint32_t sa = sb + STAGE_OFF + (uint32_t)grow * 256
                              + (uint32_t)((g_u ^ ((grow & 7) << 2)) << 3);
            float4 v;
            LDS128(v, sa);
            *(float4*)(out + (size_t)(row0 + grow) * OUT_N + col0 + (tid & 15) * 4) = v;
        }

        if (t + 2 < NT) load_C(ct0 + t + 2, buf);
        CP_COMMIT();                // keep group count aligned
    }
}

extern "C" void kernel_launch(void* const* d_in, const int* in_sizes, int n_in,
                              void* d_out, int out_size) {
    (void)in_sizes; (void)n_in; (void)out_size;
    const float* input      = (const float*)d_in[0];
    const float* centers    = (const float*)d_in[1];
    const float* log_sigmas = (const float*)d_in[2];
    float* out              = (float*)d_out;

    cudaFuncSetAttribute(rbf_hmma, cudaFuncAttributeMaxDynamicSharedMemorySize, SMEM_MAIN);

    prep_all<<<B_ROWS * 16 / 256 + OUT_N * 16 / 256, 256>>>(input, centers, log_sigmas);
    rbf_hmma<<<(B_ROWS / BM) * (OUT_N / BN / NT), NTHREADS, SMEM_MAIN>>>(out);
}

// round 14
// speedup vs baseline: 1.0930x; 1.0930x over previous
#include <cuda_runtime.h>
#include <cuda_fp16.h>
#include <cstdint>

#define B_ROWS   65536
#define OUT_N    2048
#define IN_K     64
#define BM       128
#define BN       64
#define NTHREADS 256
#define NT       8              // col tiles per CTA
#define BUFSTR   8704           // C buffer stride: 8 KB tile + 512 B aux
#define CB_OFF   16384          // 3 C buffers
#define X2S_OFF  42496          // 128 floats (exact ||x||^2)
#define XTMP_OFF 43008          // 16 KB fp32 X staging (half tile)
#define SMEM_MAIN 59392

// ---------------- scratch (__device__ globals: allocation-free) ----------------
__device__ __half g_C[(size_t)OUT_N * IN_K];
__device__ float g_c2[OUT_N];      // exact ||c||^2 (fp32)
__device__ float g_e2[OUT_N];      // -exp(-2*log_sigma) * log2(e)

// ---------------- PTX helpers (sm_80-era only) ----------------
__device__ __forceinline__ uint32_t smem_u32(const void* p) {
    uint32_t a;
    asm("{ .reg .u64 t; cvta.to.shared.u64 t, %1; cvt.u32.u64 %0, t; }" : "=r"(a) : "l"(p));
    return a;
}
__device__ __forceinline__ void cp16(uint32_t s, const void* g) {
    asm volatile("{ .reg .u64 ga; cvta.to.global.u64 ga, %1; cp.async.cg.shared.global [%0], [ga], 16; }"
                 :: "r"(s), "l"(g) : "memory");
}
#define CP_COMMIT() asm volatile("cp.async.commit_group;" ::: "memory")
#define CP_WAIT0()  asm volatile("cp.async.wait_group 0;" ::: "memory")
#define CP_WAIT1()  asm volatile("cp.async.wait_group 1;" ::: "memory")
#define CP_WAIT2()  asm volatile("cp.async.wait_group 2;" ::: "memory")

#define STS128(a, r0, r1, r2, r3) \
    asm volatile("st.shared.v4.b32 [%0], {%1,%2,%3,%4};" \
        :: "r"(a), "r"(r0), "r"(r1), "r"(r2), "r"(r3) : "memory")

#define LDSM4(r, a) \
    asm volatile("ldmatrix.sync.aligned.m8n8.x4.shared.b16 {%0,%1,%2,%3}, [%4];" \
        : "=r"((r)[0]), "=r"((r)[1]), "=r"((r)[2]), "=r"((r)[3]) : "r"(a))

#define MMA16816(d, a, b0, b1) \
    asm volatile("mma.sync.aligned.m16n8k16.row.col.f32.f16.f16.f32 " \
        "{%0,%1,%2,%3}, {%4,%5,%6,%7}, {%8,%9}, {%0,%1,%2,%3};" \
        : "+f"((d)[0]), "+f"((d)[1]), "+f"((d)[2]), "+f"((d)[3]) \
        : "r"((a)[0]), "r"((a)[1]), "r"((a)[2]), "r"((a)[3]), "r"(b0), "r"(b1))

// ---------------- prep (centers only): fp32 -> fp16 + exact norms ----------------
__global__ void prep_centers(const float* __restrict__ cen, const float* __restrict__ ls) {
    const int g = blockIdx.x * blockDim.x + threadIdx.x;   // OUT_N*16 threads
    const int row = g >> 4, seg = g & 15;
    const float4 v = *(const float4*)(cen + (size_t)row * IN_K + seg * 4);
    float vv[4] = {v.x, v.y, v.z, v.w};
    float s = 0.f;
    __half h[4];
    #pragma unroll
    for (int i = 0; i < 4; i++) {
        s = fmaf(vv[i], vv[i], s);
        h[i] = __float2half_rn(vv[i]);
    }
    uint2 hp;
    memcpy(&hp, h, 8);
    *(uint2*)(g_C + (size_t)row * IN_K + seg * 4) = hp;
    #pragma unroll
    for (int m = 1; m <= 8; m <<= 1) s += __shfl_xor_sync(~0u, s, m);
    if (seg == 0) {
        g_c2[row] = s;
        g_e2[row] = -1.4426950408889634f * expf(-2.f * ls[row]);
    }
}

// ---------------- main ----------------
// smem layout (byte offsets):
//   0      sX   : [128][64] fp16 swizzled               16384
//   16384  cbuf : 3 x (C tile 8192 + c2 256 + e2 256)   26112
//   42496  x2s  : 128 floats                              512
//   43008  xtmp : 64 rows x 64 fp32 (16 KB)             16384
extern __shared__ char smem_raw[];

__global__ __launch_bounds__(NTHREADS, 3)
void rbf_hmma(const float* __restrict__ inp, float* __restrict__ out) {
    const int tid = threadIdx.x;
    const int bid = blockIdx.x;
    const int row0 = (bid >> 2) * BM;
    const int ct0  = (bid & 3) * NT;

    const uint32_t sb  = smem_u32(smem_raw);
    const uint32_t sXu = sb;
    float* x2s = (float*)(smem_raw + X2S_OFF);
    const float* xtmp = (const float*)(smem_raw + XTMP_OFF);

    auto load_C = [&](int ct, int buf) {
        const uint32_t dst = sb + CB_OFF + buf * BUFSTR;
        #pragma unroll
        for (int i = 0; i < 2; i++) {
            int u = tid + i * NTHREADS;
            int r = u >> 3, c = u & 7;
            cp16(dst + r * 128 + ((c ^ (r & 7)) << 4),
                 g_C + (size_t)(ct * BN + r) * IN_K + c * 8);
        }
        if (tid < 16)
            cp16(dst + 8192 + tid * 16, g_c2 + ct * BN + tid * 4);
        else if (tid < 32)
            cp16(dst + 8192 + 256 + (tid - 16) * 16, g_e2 + ct * BN + (tid - 16) * 4);
    };

    // linear 16 KB fp32 copy of 64 X rows into xtmp
    auto load_Xhalf = [&](int h) {
        const float* src = inp + (size_t)(row0 + h * 64) * IN_K;
        #pragma unroll
        for (int i = 0; i < 4; i++) {
            int u = tid + i * NTHREADS;          // 0..1023 (16B units)
            cp16(sb + XTMP_OFF + u * 16, src + u * 4);
        }
    };

    // convert xtmp (64 rows fp32) -> sX rows [h*64, h*64+64), swizzled fp16;
    // also compute exact ||x||^2 into x2s.
    auto convert_Xhalf = [&](int h) {
        #pragma unroll
        for (int i = 0; i < 2; i++) {
            int u = tid + i * NTHREADS;          // 0..511
            int r = u >> 3, cu = u & 7;
            const float4* fp = (const float4*)(xtmp + r * IN_K + cu * 8);
            float4 v0 = fp[0], v1 = fp[1];
            __half2 h0 = __floats2half2_rn(v0.x, v0.y);
            __half2 h1 = __floats2half2_rn(v0.z, v0.w);
            __half2 h2 = __floats2half2_rn(v1.x, v1.y);
            __half2 h3 = __floats2half2_rn(v1.z, v1.w);
            int rg = r + h * 64;
            STS128(sXu + rg * 128 + ((cu ^ (rg & 7)) << 4),
                   *(uint32_t*)&h0, *(uint32_t*)&h1, *(uint32_t*)&h2, *(uint32_t*)&h3);
        }
        {
            int row = tid >> 2;                  // 0..63
            int q   = tid & 3;
            const float4* fp = (const float4*)(xtmp + row * IN_K + q * 16);
            float s = 0.f;
            #pragma unroll
            for (int k = 0; k < 4; k++) {
                float4 v = fp[k];
                s = fmaf(v.x, v.x, s); s = fmaf(v.y, v.y, s);
                s = fmaf(v.z, v.z, s); s = fmaf(v.w, v.w, s);
            }
            s += __shfl_xor_sync(~0u, s, 1);
            s += __shfl_xor_sync(~0u, s, 2);
            if (q == 0) x2s[h * 64 + row] = s;
        }
    };

    // ---- prologue ----
    load_Xhalf(0);            CP_COMMIT();   // G0
    load_C(ct0, 0);           CP_COMMIT();   // G1
    load_C(ct0 + 1, 1);       CP_COMMIT();   // G2
    CP_WAIT2();               // G0 (X half 0) done
    __syncthreads();
    convert_Xhalf(0);
    __syncthreads();          // all xtmp reads done before overwrite
    load_Xhalf(1);            CP_COMMIT();   // G3
    CP_WAIT0();               // everything done (X half 1, C0, C1)
    __syncthreads();
    convert_Xhalf(1);
    __syncthreads();

    // ---- warp tiling: 8 warps = 4 (M) x 2 (N); warp tile 32x32 ----
    const int l   = tid & 31;
    const int wid = tid >> 5;
    const int wr  = wid & 3;
    const int wc  = wid >> 2;

    uint32_t abase[2];
    {
        int hb = l >> 4;
        #pragma unroll
        for (int mi = 0; mi < 2; mi++) {
            int row = wr * 32 + mi * 16 + (l & 15);
            abase[mi] = row * 128 + ((hb ^ (row & 7)) << 4);
        }
    }
    uint32_t bbase[2];
    {
        int m = l >> 3;
        int hb = m & 1;
        #pragma unroll
        for (int q = 0; q < 2; q++) {
            int n = wc * 32 + (2 * q + (m >> 1)) * 8 + (l & 7);
            bbase[q] = n * 128 + ((hb ^ (n & 7)) << 4);
        }
    }

    #pragma unroll 1
    for (int t = 0; t < NT; t++) {
        const int buf = t % 3;
        const uint32_t cbuf = sb + CB_OFF + buf * BUFSTR;
        const int col0 = (ct0 + t) * BN;

        CP_WAIT1();                 // C_t ready (only newest group may pend)
        __syncthreads();            // single barrier per tile

        float acc[2][4][4];
        #pragma unroll
        for (int mi = 0; mi < 2; mi++)
            #pragma unroll
            for (int j = 0; j < 4; j++)
                #pragma unroll
                for (int q = 0; q < 4; q++) acc[mi][j][q] = 0.f;

        #pragma unroll
        for (int ks = 0; ks < 4; ks++) {
            const uint32_t kx = (uint32_t)ks << 5;
            uint32_t a[2][4], b[2][4];
            LDSM4(a[0], sXu + (abase[0] ^ kx));
            LDSM4(a[1], sXu + (abase[1] ^ kx));
            LDSM4(b[0], cbuf + (bbase[0] ^ kx));
            LDSM4(b[1], cbuf + (bbase[1] ^ kx));
            #pragma unroll
            for (int j = 0; j < 4; j++) {
                uint32_t b0 = b[j >> 1][(j & 1) * 2];
                uint32_t b1 = b[j >> 1][(j & 1) * 2 + 1];
                MMA16816(acc[0][j], a[0], b0, b1);
                MMA16816(acc[1][j], a[1], b0, b1);
            }
        }

        // ---- prefetch C_{t+2} right away (no barrier needed: its buffer was
        //      last read at tile t-1, ordered by this tile's top barrier) ----
        if (t + 2 < NT) load_C(ct0 + t + 2, (t + 2) % 3);
        CP_COMMIT();

        // ---- epilogue: out = exp2((x2 - 2*dot + c2) * e2), scattered STG.64 ----
        const float* c2s = (const float*)(smem_raw + CB_OFF + buf * BUFSTR + 8192);
        const float* e2s = c2s + 64;
        #pragma unroll
        for (int mi = 0; mi < 2; mi++) {
            const int rl = wr * 32 + mi * 16 + (l >> 2);
            const float x2a = x2s[rl];
            const float x2b = x2s[rl + 8];
            float* o0 = out + (size_t)(row0 + rl) * OUT_N + col0;
            float* o1 = o0 + 8 * OUT_N;
            #pragma unroll
            for (int j = 0; j < 4; j++) {
                const int c = wc * 32 + j * 8 + 2 * (l & 3);
                const float c20 = c2s[c],  c21 = c2s[c + 1];
                const float e0  = e2s[c],  e1  = e2s[c + 1];
                const float* A  = acc[mi][j];
                float s0 = fmaxf(fmaf(-2.f, A[0], x2a + c20), 0.f);
                float s1 = fmaxf(fmaf(-2.f, A[1], x2a + c21), 0.f);
                float s2 = fmaxf(fmaf(-2.f, A[2], x2b + c20), 0.f);
                float s3 = fmaxf(fmaf(-2.f, A[3], x2b + c21), 0.f);
                *(float2*)(o0 + c) = make_float2(exp2f(s0 * e0), exp2f(s1 * e1));
                *(float2*)(o1 + c) = make_float2(exp2f(s2 * e0), exp2f(s3 * e1));
            }
        }
    }
}

extern "C" void kernel_launch(void* const* d_in, const int* in_sizes, int n_in,
                              void* d_out, int out_size) {
    (void)in_sizes; (void)n_in; (void)out_size;
    const float* input      = (const float*)d_in[0];
    const float* centers    = (const float*)d_in[1];
    const float* log_sigmas = (const float*)d_in[2];
    float* out              = (float*)d_out;

    cudaFuncSetAttribute(rbf_hmma, cudaFuncAttributeMaxDynamicSharedMemorySize, SMEM_MAIN);

    prep_centers<<<OUT_N * 16 / 256, 256>>>(centers, log_sigmas);
    rbf_hmma<<<(B_ROWS / BM) * (OUT_N / BN / NT), NTHREADS, SMEM_MAIN>>>(input, out);
}

// round 16
// speedup vs baseline: 1.2935x; 1.1834x over previous
#include <cuda_runtime.h>
#include <cuda_fp16.h>
#include <cstdint>

#define B_ROWS   65536
#define OUT_N    2048
#define IN_K     64
#define BM       128
#define BN       64
#define NTHREADS 256
#define NT       8              // col tiles per CTA
#define BUFSTR   8704           // C buffer stride: 8 KB tile + 512 B aux
#define SMEM_MAIN 34304

// ---------------- scratch (__device__ globals: allocation-free) ----------------
__device__ __half g_X[(size_t)B_ROWS * IN_K];
__device__ __half g_C[(size_t)OUT_N * IN_K];
__device__ float g_x2[B_ROWS];     // exact ||x||^2 (fp32)
__device__ float g_c2[OUT_N];      // exact ||c||^2 (fp32)
__device__ float g_e2[OUT_N];      // -exp(-2*log_sigma) * log2(e)

// ---------------- PTX helpers (sm_80-era only) ----------------
__device__ __forceinline__ uint32_t smem_u32(const void* p) {
    uint32_t a;
    asm("{ .reg .u64 t; cvta.to.shared.u64 t, %1; cvt.u32.u64 %0, t; }" : "=r"(a) : "l"(p));
    return a;
}
__device__ __forceinline__ void cp16(uint32_t s, const void* g) {
    asm volatile("{ .reg .u64 ga; cvta.to.global.u64 ga, %1; cp.async.cg.shared.global [%0], [ga], 16; }"
                 :: "r"(s), "l"(g) : "memory");
}
#define CP_COMMIT() asm volatile("cp.async.commit_group;" ::: "memory")
#define CP_WAIT1()  asm volatile("cp.async.wait_group 1;" ::: "memory")

#define LDSM4(r, a) \
    asm volatile("ldmatrix.sync.aligned.m8n8.x4.shared.b16 {%0,%1,%2,%3}, [%4];" \
        : "=r"((r)[0]), "=r"((r)[1]), "=r"((r)[2]), "=r"((r)[3]) : "r"(a))

#define MMA16816(d, a, b0, b1) \
    asm volatile("mma.sync.aligned.m16n8k16.row.col.f32.f16.f16.f32 " \
        "{%0,%1,%2,%3}, {%4,%5,%6,%7}, {%8,%9}, {%0,%1,%2,%3};" \
        : "+f"((d)[0]), "+f"((d)[1]), "+f"((d)[2]), "+f"((d)[3]) \
        : "r"((a)[0]), "r"((a)[1]), "r"((a)[2]), "r"((a)[3]), "r"(b0), "r"(b1))

// ---------------- prep: fp32 -> fp16 + exact norms (MLP=2 per thread) ----------------
// blocks [0, 2048): input rows (8 threads/row); blocks [2048, 2112): center rows.
__global__ void prep_all(const float* __restrict__ inp,
                         const float* __restrict__ cen,
                         const float* __restrict__ ls) {
    const int b = blockIdx.x;
    const bool is_c = (b >= 2048);
    const int g = (is_c ? (b - 2048) : b) * blockDim.x + threadIdx.x;
    const int row = g >> 3, seg = g & 7;     // thread covers float4 #seg and #(seg+8)

    const float* src = (is_c ? cen : inp) + (size_t)row * IN_K;
    const float4 v0 = *(const float4*)(src + seg * 4);
    const float4 v1 = *(const float4*)(src + 32 + seg * 4);
    float s = 0.f;
    __half ha[4], hb[4];
    {
        float a[4] = {v0.x, v0.y, v0.z, v0.w};
        float c[4] = {v1.x, v1.y, v1.z, v1.w};
        #pragma unroll
        for (int i = 0; i < 4; i++) {
            s = fmaf(a[i], a[i], s);
            s = fmaf(c[i], c[i], s);
            ha[i] = __float2half_rn(a[i]);
            hb[i] = __float2half_rn(c[i]);
        }
    }
    uint2 pa, pb;
    memcpy(&pa, ha, 8); memcpy(&pb, hb, 8);
    const size_t base = (size_t)row * IN_K + seg * 4;
    if (is_c) {
        *(uint2*)(g_C + base)      = pa;
        *(uint2*)(g_C + base + 32) = pb;
    } else {
        *(uint2*)(g_X + base)      = pa;
        *(uint2*)(g_X + base + 32) = pb;
    }
    s += __shfl_xor_sync(~0u, s, 1);
    s += __shfl_xor_sync(~0u, s, 2);
    s += __shfl_xor_sync(~0u, s, 4);
    if (seg == 0) {
        if (is_c) {
            g_c2[row] = s;
            g_e2[row] = -1.4426950408889634f * expf(-2.f * ls[row]);
        } else {
            g_x2[row] = s;
        }
    }
}

// ---------------- main: R8 skeleton + shuffle-packed STG.128 epilogue ----------------
// smem layout (byte offsets):
//   0      sX  : [128][64] fp16 swizzled                    16384
//   16384  buf0: C tile 8192 + c2 256 + e2 256               8704
//   25088  buf1: same                                         8704
//   33792  x2s : 128 floats                                    512
extern __shared__ char smem_raw[];

__global__ __launch_bounds__(NTHREADS, 3)
void rbf_hmma(float* __restrict__ out) {
    const int tid = threadIdx.x;
    const int bid = blockIdx.x;
    const int row0 = (bid >> 2) * BM;
    const int ct0  = (bid & 3) * NT;

    const uint32_t sb  = smem_u32(smem_raw);
    const uint32_t sXu = sb;
    float* x2s = (float*)(smem_raw + 33792);

    auto load_C = [&](int ct, int buf) {
        const uint32_t dst = sb + 16384 + buf * BUFSTR;
        #pragma unroll
        for (int i = 0; i < 2; i++) {
            int u = tid + i * NTHREADS;
            int r = u >> 3, c = u & 7;
            cp16(dst + r * 128 + ((c ^ (r & 7)) << 4),
                 g_C + (size_t)(ct * BN + r) * IN_K + c * 8);
        }
        if (tid < 16)
            cp16(dst + 8192 + tid * 16, g_c2 + ct * BN + tid * 4);
        else if (tid < 32)
            cp16(dst + 8192 + 256 + (tid - 16) * 16, g_e2 + ct * BN + (tid - 16) * 4);
    };

    // ---- prologue: X + x2 + C0 (group 0), C1 (group 1) ----
    #pragma unroll
    for (int i = 0; i < 4; i++) {
        int u = tid + i * NTHREADS;
        int r = u >> 3, c = u & 7;
        cp16(sXu + r * 128 + ((c ^ (r & 7)) << 4),
             g_X + (size_t)(row0 + r) * IN_K + c * 8);
    }
    if (tid < 32) cp16(sb + 33792 + tid * 16, g_x2 + row0 + tid * 4);
    load_C(ct0, 0);
    CP_COMMIT();
    load_C(ct0 + 1, 1);
    CP_COMMIT();

    // ---- warp tiling: 8 warps = 4 (M) x 2 (N); warp tile 32x32 ----
    const int l   = tid & 31;
    const int wid = tid >> 5;
    const int wr  = wid & 3;
    const int wc  = wid >> 2;

    uint32_t abase[2];
    {
        int hb = l >> 4;
        #pragma unroll
        for (int mi = 0; mi < 2; mi++) {
            int row = wr * 32 + mi * 16 + (l & 15);
            abase[mi] = row * 128 + ((hb ^ (row & 7)) << 4);
        }
    }
    uint32_t bbase[2];
    {
        int m = l >> 3;
        int hb = m & 1;
        #pragma unroll
        for (int q = 0; q < 2; q++) {
            int n = wc * 32 + (2 * q + (m >> 1)) * 8 + (l & 7);
            bbase[q] = n * 128 + ((hb ^ (n & 7)) << 4);
        }
    }

    // packed-epilogue column bases (per jp group): 4 contiguous floats per thread
    //   cn[jp] = (2*jp + (l&1))*8 + ((l>>1)&1)*4, within the warp's 32-col tile
    const int cn0 = ((l & 1) << 3) + ((l >> 1) & 1) * 4;
    const int cn1 = cn0 + 16;

    #pragma unroll 1
    for (int t = 0; t < NT; t++) {
        const int buf = t & 1;
        const uint32_t cbuf = sb + 16384 + buf * BUFSTR;
        const int col0 = (ct0 + t) * BN;

        CP_WAIT1();                 // current buf's load complete
        __syncthreads();

        float acc[2][4][4];
        #pragma unroll
        for (int mi = 0; mi < 2; mi++)
            #pragma unroll
            for (int j = 0; j < 4; j++)
                #pragma unroll
                for (int q = 0; q < 4; q++) acc[mi][j][q] = 0.f;

        #pragma unroll
        for (int ks = 0; ks < 4; ks++) {
            const uint32_t kx = (uint32_t)ks << 5;
            uint32_t a[2][4], b[2][4];
            LDSM4(a[0], sXu + (abase[0] ^ kx));
            LDSM4(a[1], sXu + (abase[1] ^ kx));
            LDSM4(b[0], cbuf + (bbase[0] ^ kx));
            LDSM4(b[1], cbuf + (bbase[1] ^ kx));
            #pragma unroll
            for (int j = 0; j < 4; j++) {
                uint32_t b0 = b[j >> 1][(j & 1) * 2];
                uint32_t b1 = b[j >> 1][(j & 1) * 2 + 1];
                MMA16816(acc[0][j], a[0], b0, b1);
                MMA16816(acc[1][j], a[1], b0, b1);
            }
        }

        // ---- epilogue: butterfly-pack dots to 4 contiguous cols, STG.128 ----
        const float* c2s = (const float*)(smem_raw + 16384 + buf * BUFSTR + 8192);
        const float* e2s = c2s + 64;
        const float4 c2v0 = *(const float4*)(c2s + wc * 32 + cn0);
        const float4 e2v0 = *(const float4*)(e2s + wc * 32 + cn0);
        const float4 c2v1 = *(const float4*)(c2s + wc * 32 + cn1);
        const float4 e2v1 = *(const float4*)(e2s + wc * 32 + cn1);

        #pragma unroll
        for (int mi = 0; mi < 2; mi++) {
            const int rl = wr * 32 + mi * 16 + (l >> 2);
            const float x2a = x2s[rl];
            const float x2b = x2s[rl + 8];
            float* oa = out + (size_t)(row0 + rl) * OUT_N + col0 + wc * 32;
            float* ob = oa + 8 * OUT_N;
            #pragma unroll
            for (int jp = 0; jp < 2; jp++) {
                const int jlo = jp * 2, jhi = jp * 2 + 1;
                // exchange: even lane sends jhi(cols +0,+1), odd sends jlo(cols +2,+3)
                float sa0 = (l & 1) ? acc[mi][jlo][0] : acc[mi][jhi][0];
                float sa1 = (l & 1) ? acc[mi][jlo][1] : acc[mi][jhi][1];
                float sb0 = (l & 1) ? acc[mi][jlo][2] : acc[mi][jhi][2];
                float sb1 = (l & 1) ? acc[mi][jlo][3] : acc[mi][jhi][3];
                sa0 = __shfl_xor_sync(~0u, sa0, 1);
                sa1 = __shfl_xor_sync(~0u, sa1, 1);
                sb0 = __shfl_xor_sync(~0u, sb0, 1);
                sb1 = __shfl_xor_sync(~0u, sb1, 1);
                float da[4], db[4];
                if (l & 1) {
                    da[0] = sa0; da[1] = sa1; da[2] = acc[mi][jhi][0]; da[3] = acc[mi][jhi][1];
                    db[0] = sb0; db[1] = sb1; db[2] = acc[mi][jhi][2]; db[3] = acc[mi][jhi][3];
                } else {
                    da[0] = acc[mi][jlo][0]; da[1] = acc[mi][jlo][1]; da[2] = sa0; da[3] = sa1;
                    db[0] = acc[mi][jlo][2]; db[1] = acc[mi][jlo][3]; db[2] = sb0; db[3] = sb1;
                }
                const float4 c2v = jp ? c2v1 : c2v0;
                const float4 e2v = jp ? e2v1 : e2v0;
                const int cn = jp ? cn1 : cn0;
                float4 ra, rb;
                ra.x = exp2f(fmaxf(fmaf(-2.f, da[0], x2a + c2v.x), 0.f) * e2v.x);
                ra.y = exp2f(fmaxf(fmaf(-2.f, da[1], x2a + c2v.y), 0.f) * e2v.y);
                ra.z = exp2f(fmaxf(fmaf(-2.f, da[2], x2a + c2v.z), 0.f) * e2v.z);
                ra.w = exp2f(fmaxf(fmaf(-2.f, da[3], x2a + c2v.w), 0.f) * e2v.w);
                rb.x = exp2f(fmaxf(fmaf(-2.f, db[0], x2b + c2v.x), 0.f) * e2v.x);
                rb.y = exp2f(fmaxf(fmaf(-2.f, db[1], x2b + c2v.y), 0.f) * e2v.y);
                rb.z = exp2f(fmaxf(fmaf(-2.f, db[2], x2b + c2v.z), 0.f) * e2v.z);
                rb.w = exp2f(fmaxf(fmaf(-2.f, db[3], x2b + c2v.w), 0.f) * e2v.w);
                *(float4*)(oa + cn) = ra;
                *(float4*)(ob + cn) = rb;
            }
        }

        __syncthreads();            // all reads of buf done before overwrite
        if (t + 2 < NT) load_C(ct0 + t + 2, buf);
        CP_COMMIT();                // keep group count aligned
    }
}

extern "C" void kernel_launch(void* const* d_in, const int* in_sizes, int n_in,
                              void* d_out, int out_size) {
    (void)in_sizes; (void)n_in; (void)out_size;
    const float* input      = (const float*)d_in[0];
    const float* centers    = (const float*)d_in[1];
    const float* log_sigmas = (const float*)d_in[2];
    float* out              = (float*)d_out;

    cudaFuncSetAttribute(rbf_hmma, cudaFuncAttributeMaxDynamicSharedMemorySize, SMEM_MAIN);

    prep_all<<<B_ROWS * 8 / 256 + OUT_N * 8 / 256, 256>>>(input, centers, log_sigmas);
    rbf_hmma<<<(B_ROWS / BM) * (OUT_N / BN / NT), NTHREADS, SMEM_MAIN>>>(out);
}